// round 16
// baseline (speedup 1.0000x reference)
#include <cuda_runtime.h>

#define B_ 64
#define N_ 4096
#define D_ 256
#define S_ 8
#define H_ 512
#define CH_ 32

// ---------------- scratch (device globals; no allocation allowed) ----------------
__device__ float g_xn[B_*N_*D_];        // LN(inputs)
__device__ float g_slots[B_*S_*D_];
__device__ float g_qt[B_*S_*D_];        // q~ = (q @ Wk)
__device__ float g_upd[B_*S_*D_];       // updates = u @ Wv^T
__device__ float g_updp[B_*CH_*S_*D_];  // partials of u = attn^T @ xn
__device__ float g_colp[B_*CH_*S_];
__device__ float g_gi[B_*S_*768];
__device__ float g_gh[B_*S_*768];
__device__ float g_ns[B_*S_*D_];
__device__ float g_h1[B_*S_*H_];

// ---------------- helpers --------------------------------------------------------
__device__ __forceinline__ void mma_tf32(float& c0, float& c1, float& c2, float& c3,
                                         unsigned a0, unsigned a1, unsigned a2, unsigned a3,
                                         unsigned b0, unsigned b1) {
    asm volatile(
        "mma.sync.aligned.m16n8k8.row.col.f32.tf32.tf32.f32 "
        "{%0,%1,%2,%3}, {%4,%5,%6,%7}, {%8,%9}, {%0,%1,%2,%3};"
        : "+f"(c0), "+f"(c1), "+f"(c2), "+f"(c3)
        : "r"(a0), "r"(a1), "r"(a2), "r"(a3), "r"(b0), "r"(b1));
}

// =================================================================================
// K0: slots = mu + exp(log_sigma) * noise
// =================================================================================
__global__ void k0_init(const float* __restrict__ noise,
                        const float* __restrict__ mu,
                        const float* __restrict__ ls) {
    int i = blockIdx.x * 256 + threadIdx.x;
    int d = i & 255;
    g_slots[i] = mu[d] + expf(ls[d]) * noise[i];
}

// =================================================================================
// K1: xn = LayerNorm(inputs).  grid 2048, 256 threads (2/token).
// =================================================================================
__global__ void __launch_bounds__(256) k1_ln(
    const float* __restrict__ inp, const float* __restrict__ lnw,
    const float* __restrict__ lnb)
{
    int tid = threadIdx.x;
    long tok0 = (long)blockIdx.x * 128;
    int tok = tid >> 1, half = tid & 1;
    const float4* xr = (const float4*)(inp + (tok0 + tok) * 256 + half * 128);
    float4 t[32];
    float s1 = 0.f, s2 = 0.f;
#pragma unroll
    for (int j = 0; j < 32; j++) {
        t[j] = xr[j];
        s1 += t[j].x + t[j].y + t[j].z + t[j].w;
        s2 += t[j].x*t[j].x + t[j].y*t[j].y + t[j].z*t[j].z + t[j].w*t[j].w;
    }
    s1 += __shfl_xor_sync(0xffffffffu, s1, 1);
    s2 += __shfl_xor_sync(0xffffffffu, s2, 1);
    float mean = s1 * (1.0f / 256.0f);
    float var  = s2 * (1.0f / 256.0f) - mean * mean;
    float rs   = rsqrtf(var + 1e-5f);
    const float4* lw4 = (const float4*)(lnw + half * 128);
    const float4* lb4 = (const float4*)(lnb + half * 128);
    float4* xw = (float4*)(g_xn + (tok0 + tok) * 256 + half * 128);
#pragma unroll
    for (int j = 0; j < 32; j++) {
        float4 w4 = __ldg(lw4 + j);
        float4 b4 = __ldg(lb4 + j);
        float4 o;
        o.x = (t[j].x - mean) * rs * w4.x + b4.x;
        o.y = (t[j].y - mean) * rs * w4.y + b4.y;
        o.z = (t[j].z - mean) * rs * w4.z + b4.z;
        o.w = (t[j].w - mean) * rs * w4.w + b4.w;
        xw[j] = o;
    }
}

// =================================================================================
// K3: initial q~ (before the loop only).  grid 64, 256 threads.
// =================================================================================
__global__ void __launch_bounds__(256) k3_q(
    const float* __restrict__ Wq, const float* __restrict__ Wk,
    const float* __restrict__ lnw, const float* __restrict__ lnb)
{
    __shared__ float sn[8 * 256];
    __shared__ float qsm[8 * 256];
    int tid = threadIdx.x, b = blockIdx.x;
    int r = tid >> 5, l = tid & 31;

    const float4* sr = (const float4*)(g_slots + (b * 8 + r) * 256);
    float4 v0 = sr[l * 2], v1 = sr[l * 2 + 1];
    float s1 = v0.x + v0.y + v0.z + v0.w + v1.x + v1.y + v1.z + v1.w;
    float s2 = v0.x*v0.x + v0.y*v0.y + v0.z*v0.z + v0.w*v0.w
             + v1.x*v1.x + v1.y*v1.y + v1.z*v1.z + v1.w*v1.w;
#pragma unroll
    for (int off = 16; off >= 1; off >>= 1) {
        s1 += __shfl_xor_sync(0xffffffffu, s1, off);
        s2 += __shfl_xor_sync(0xffffffffu, s2, off);
    }
    float mean = s1 * (1.0f / 256.0f);
    float var  = s2 * (1.0f / 256.0f) - mean * mean;
    float rs   = rsqrtf(var + 1e-5f);
    int d0 = l * 8;
    sn[r*256 + d0 + 0] = (v0.x - mean) * rs * lnw[d0+0] + lnb[d0+0];
    sn[r*256 + d0 + 1] = (v0.y - mean) * rs * lnw[d0+1] + lnb[d0+1];
    sn[r*256 + d0 + 2] = (v0.z - mean) * rs * lnw[d0+2] + lnb[d0+2];
    sn[r*256 + d0 + 3] = (v0.w - mean) * rs * lnw[d0+3] + lnb[d0+3];
    sn[r*256 + d0 + 4] = (v1.x - mean) * rs * lnw[d0+4] + lnb[d0+4];
    sn[r*256 + d0 + 5] = (v1.y - mean) * rs * lnw[d0+5] + lnb[d0+5];
    sn[r*256 + d0 + 6] = (v1.z - mean) * rs * lnw[d0+6] + lnb[d0+6];
    sn[r*256 + d0 + 7] = (v1.w - mean) * rs * lnw[d0+7] + lnb[d0+7];
    __syncthreads();

    {
        float acc[8] = {0,0,0,0,0,0,0,0};
        const float4* wr  = (const float4*)(Wq + tid * 256);
        const float4* sn4 = (const float4*)sn;
        for (int d4 = 0; d4 < 64; d4++) {
            float4 w = wr[d4];
#pragma unroll
            for (int rr = 0; rr < 8; rr++) {
                float4 s = sn4[rr * 64 + d4];
                acc[rr] += w.x*s.x + w.y*s.y + w.z*s.z + w.w*s.w;
            }
        }
        const float scale = 0.0625f;
#pragma unroll
        for (int rr = 0; rr < 8; rr++) qsm[rr * 256 + tid] = acc[rr] * scale;
    }
    __syncthreads();

    {
        float a2[8] = {0,0,0,0,0,0,0,0};
#pragma unroll 4
        for (int d = 0; d < 256; d++) {
            float w = __ldg(Wk + d * 256 + tid);
#pragma unroll
            for (int s = 0; s < 8; s++) a2[s] += qsm[s * 256 + d] * w;
        }
#pragma unroll
        for (int s = 0; s < 8; s++)
            g_qt[(b * 8 + s) * 256 + tid] = a2[s];
    }
}

// =================================================================================
// K4: smem-free tf32 streaming attention on xn (R12 verbatim, occ 4).  grid (32,64).
// =================================================================================
__global__ void __launch_bounds__(256, 4) k4_attn()
{
    __shared__ float at[16 * 132];
    __shared__ unsigned qt[256 * 8];
    __shared__ float wcs[8][8];
    unsigned* atu = (unsigned*)at;

    int tid = threadIdx.x;
    int w = tid >> 5, lane = tid & 31;
    int g = lane >> 2, c = lane & 3;
    int b = blockIdx.y, chunk = blockIdx.x;
    long tok0 = (long)b * 4096 + (long)chunk * 128;

    for (int i = tid; i < 2048; i += 256) {
        int s = i >> 8, d = i & 255;
        qt[d * 8 + s] = __float_as_uint(g_qt[b * 2048 + i]);
    }
    for (int i = tid; i < 8 * 132; i += 256) at[8 * 132 + i] = 0.f;
    __syncthreads();

    {   // phase 1: warp w -> tokens [w*16, w*16+16)
        int m0 = w * 16;
        const unsigned* kb = (const unsigned*)(g_xn + tok0 * 256);
        int rA = (m0 + g) * 256, rB = (m0 + g + 8) * 256;
        float c0 = 0.f, c1 = 0.f, c2 = 0.f, c3 = 0.f;
#pragma unroll 8
        for (int ks = 0; ks < 32; ks++) {
            int k0 = ks * 8;
            unsigned a0 = kb[rA + k0 + c];
            unsigned a1 = kb[rB + k0 + c];
            unsigned a2 = kb[rA + k0 + c + 4];
            unsigned a3 = kb[rB + k0 + c + 4];
            unsigned b0 = qt[(k0 + c) * 8 + g];
            unsigned b1 = qt[(k0 + c + 4) * 8 + g];
            mma_tf32(c0, c1, c2, c3, a0, a1, a2, a3, b0, b1);
        }
        float cs0 = 0.f, cs1 = 0.f;
        {
            float m1 = fmaxf(c0, c1);
            m1 = fmaxf(m1, __shfl_xor_sync(0xffffffffu, m1, 1));
            m1 = fmaxf(m1, __shfl_xor_sync(0xffffffffu, m1, 2));
            float e0 = expf(c0 - m1), e1 = expf(c1 - m1);
            float sv = e0 + e1;
            sv += __shfl_xor_sync(0xffffffffu, sv, 1);
            sv += __shfl_xor_sync(0xffffffffu, sv, 2);
            float inv = 1.0f / sv;
            float w0 = e0 * inv + 1e-8f, w1v = e1 * inv + 1e-8f;
            at[(2*c)   * 132 + m0 + g] = w0;
            at[(2*c+1) * 132 + m0 + g] = w1v;
            cs0 += w0; cs1 += w1v;
        }
        {
            float m1 = fmaxf(c2, c3);
            m1 = fmaxf(m1, __shfl_xor_sync(0xffffffffu, m1, 1));
            m1 = fmaxf(m1, __shfl_xor_sync(0xffffffffu, m1, 2));
            float e0 = expf(c2 - m1), e1 = expf(c3 - m1);
            float sv = e0 + e1;
            sv += __shfl_xor_sync(0xffffffffu, sv, 1);
            sv += __shfl_xor_sync(0xffffffffu, sv, 2);
            float inv = 1.0f / sv;
            float w0 = e0 * inv + 1e-8f, w1v = e1 * inv + 1e-8f;
            at[(2*c)   * 132 + m0 + g + 8] = w0;
            at[(2*c+1) * 132 + m0 + g + 8] = w1v;
            cs0 += w0; cs1 += w1v;
        }
        cs0 += __shfl_xor_sync(0xffffffffu, cs0, 4);
        cs1 += __shfl_xor_sync(0xffffffffu, cs1, 4);
        cs0 += __shfl_xor_sync(0xffffffffu, cs0, 8);
        cs1 += __shfl_xor_sync(0xffffffffu, cs1, 8);
        cs0 += __shfl_xor_sync(0xffffffffu, cs0, 16);
        cs1 += __shfl_xor_sync(0xffffffffu, cs1, 16);
        if (g == 0) { wcs[w][2*c] = cs0; wcs[w][2*c + 1] = cs1; }
    }
    __syncthreads();
    if (tid < 8) {
        float s = 0.f;
#pragma unroll
        for (int wi = 0; wi < 8; wi++) s += wcs[wi][tid];
        g_colp[(b * CH_ + chunk) * 8 + tid] = s;
    }

    {   // phase 2: warp w -> dims [w*32, w*32+32) (same xn tile, L2-hot)
        const unsigned* vb = (const unsigned*)(g_xn + tok0 * 256);
        float acc[4][4];
#pragma unroll
        for (int nt = 0; nt < 4; nt++)
#pragma unroll
            for (int e = 0; e < 4; e++) acc[nt][e] = 0.f;
#pragma unroll 2
        for (int ks = 0; ks < 16; ks++) {
            int k0 = ks * 8;
            unsigned a0 = atu[g * 132 + k0 + c];
            unsigned a1 = atu[(g + 8) * 132 + k0 + c];
            unsigned a2 = atu[g * 132 + k0 + c + 4];
            unsigned a3 = atu[(g + 8) * 132 + k0 + c + 4];
            int rc = (k0 + c) * 256, rc4 = (k0 + c + 4) * 256;
#pragma unroll
            for (int nt = 0; nt < 4; nt++) {
                int n0 = w * 32 + nt * 8 + g;
                unsigned b0 = vb[rc + n0];
                unsigned b1 = vb[rc4 + n0];
                mma_tf32(acc[nt][0], acc[nt][1], acc[nt][2], acc[nt][3],
                         a0, a1, a2, a3, b0, b1);
            }
        }
        float* op = g_updp + ((long)(b * CH_ + chunk) * 8 + g) * 256;
#pragma unroll
        for (int nt = 0; nt < 4; nt++) {
            int n0 = w * 32 + nt * 8;
            *(float2*)(op + n0 + 2 * c) = make_float2(acc[nt][0], acc[nt][1]);
        }
    }
}

// =================================================================================
// K5: chunk-reduce + colsum-normalize + updates = u @ Wv^T  (ONCE).  grid 64.
// =================================================================================
__global__ void __launch_bounds__(256) k5_fold(const float* __restrict__ Wv)
{
    __shared__ float up[2048], cs[8];
    int tid = threadIdx.x, b = blockIdx.x;

    {
        int s = tid >> 5, l = tid & 31;
        float c = g_colp[(b * CH_ + l) * 8 + s];
#pragma unroll
        for (int off = 16; off >= 1; off >>= 1)
            c += __shfl_xor_sync(0xffffffffu, c, off);
        if (l == 0) cs[s] = c;
    }
    __syncthreads();

    for (int i = tid; i < 2048; i += 256) {
        const float* p = g_updp + (long)b * CH_ * 2048 + i;
        float a = 0.f;
#pragma unroll 8
        for (int ch = 0; ch < CH_; ch++) a += p[ch * 2048];
        up[i] = a / cs[i >> 8];
    }
    __syncthreads();

    {   // updates = u @ Wv^T
        float au[8] = {0,0,0,0,0,0,0,0};
        const float4* wv4 = (const float4*)(Wv + tid * 256);
        const float4* up4 = (const float4*)up;
        for (int d4 = 0; d4 < 64; d4++) {
            float4 wv = wv4[d4];
#pragma unroll
            for (int r = 0; r < 8; r++) {
                float4 u = up4[r * 64 + d4];
                au[r] += wv.x*u.x + wv.y*u.y + wv.z*u.z + wv.w*u.w;
            }
        }
#pragma unroll
        for (int r = 0; r < 8; r++)
            g_upd[(b * 8 + r) * 256 + tid] = au[r];
    }
}

// =================================================================================
// K6a: GRU gemms only.  grid (64, 3), 256 threads.
// =================================================================================
__global__ void __launch_bounds__(256) k6a_gru_gemm(
    const float* __restrict__ w_ih, const float* __restrict__ w_hh,
    const float* __restrict__ b_ih, const float* __restrict__ b_hh)
{
    __shared__ float updm[2048], hp[2048];
    int tid = threadIdx.x, b = blockIdx.x, m = blockIdx.y;

    for (int i = tid; i < 2048; i += 256) {
        updm[i] = g_upd[b * 2048 + i];
        hp[i]   = g_slots[b * 2048 + i];
    }
    __syncthreads();

    int o = m * 256 + tid;
    float ai[8] = {0,0,0,0,0,0,0,0};
    float ah[8] = {0,0,0,0,0,0,0,0};
    const float4* wi = (const float4*)(w_ih + o * 256);
    const float4* wh = (const float4*)(w_hh + o * 256);
    const float4* ud4 = (const float4*)updm;
    const float4* hp4 = (const float4*)hp;
    for (int d4 = 0; d4 < 64; d4++) {
        float4 a = wi[d4];
        float4 cH = wh[d4];
#pragma unroll
        for (int r = 0; r < 8; r++) {
            float4 u = ud4[r * 64 + d4];
            float4 h = hp4[r * 64 + d4];
            ai[r] += a.x*u.x + a.y*u.y + a.z*u.z + a.w*u.w;
            ah[r] += cH.x*h.x + cH.y*h.y + cH.z*h.z + cH.w*h.w;
        }
    }
    float bi = b_ih[o], bh = b_hh[o];
#pragma unroll
    for (int r = 0; r < 8; r++) {
        g_gi[(b * 8 + r) * 768 + o] = ai[r] + bi;
        g_gh[(b * 8 + r) * 768 + o] = ah[r] + bh;
    }
}

// =================================================================================
// K6bc: gates + LN (recomputed per y-block) + MLP1 slice.  grid (64, 2), 256 thr.
// =================================================================================
__global__ void __launch_bounds__(256) k6bc_gate_ln_mlp1(
    const float* __restrict__ lnw, const float* __restrict__ lnb,
    const float* __restrict__ w1,  const float* __restrict__ b1)
{
    __shared__ float ns[2048];
    __shared__ float sn[2048];
    int tid = threadIdx.x, b = blockIdx.x, m = blockIdx.y;
    int d = tid;
#pragma unroll
    for (int r = 0; r < 8; r++) {
        long base = (long)(b * 8 + r) * 768;
        float ir = g_gi[base + d],       hr = g_gh[base + d];
        float iz = g_gi[base + 256 + d], hz = g_gh[base + 256 + d];
        float in_ = g_gi[base + 512 + d], hn = g_gh[base + 512 + d];
        float rg = 1.0f / (1.0f + expf(-(ir + hr)));
        float zg = 1.0f / (1.0f + expf(-(iz + hz)));
        float ng = tanhf(in_ + rg * hn);
        float h = g_slots[(b * 8 + r) * 256 + d];
        float nsv = (1.0f - zg) * ng + zg * h;
        ns[r * 256 + d] = nsv;
        if (m == 0) g_ns[(b * 8 + r) * 256 + d] = nsv;
    }
    __syncthreads();

    {   // LN(ns) -> sn (smem only)
        int r = tid >> 5, l = tid & 31;
        const float4* nr = (const float4*)(ns + r * 256);
        float4 v0 = nr[l * 2], v1 = nr[l * 2 + 1];
        float s1 = v0.x + v0.y + v0.z + v0.w + v1.x + v1.y + v1.z + v1.w;
        float s2 = v0.x*v0.x + v0.y*v0.y + v0.z*v0.z + v0.w*v0.w
                 + v1.x*v1.x + v1.y*v1.y + v1.z*v1.z + v1.w*v1.w;
#pragma unroll
        for (int off = 16; off >= 1; off >>= 1) {
            s1 += __shfl_xor_sync(0xffffffffu, s1, off);
            s2 += __shfl_xor_sync(0xffffffffu, s2, off);
        }
        float mean = s1 * (1.0f / 256.0f);
        float var  = s2 * (1.0f / 256.0f) - mean * mean;
        float rs   = rsqrtf(var + 1e-5f);
        int d0 = l * 8;
        sn[r*256 + d0 + 0] = (v0.x - mean) * rs * lnw[d0+0] + lnb[d0+0];
        sn[r*256 + d0 + 1] = (v0.y - mean) * rs * lnw[d0+1] + lnb[d0+1];
        sn[r*256 + d0 + 2] = (v0.z - mean) * rs * lnw[d0+2] + lnb[d0+2];
        sn[r*256 + d0 + 3] = (v0.w - mean) * rs * lnw[d0+3] + lnb[d0+3];
        sn[r*256 + d0 + 4] = (v1.x - mean) * rs * lnw[d0+4] + lnb[d0+4];
        sn[r*256 + d0 + 5] = (v1.y - mean) * rs * lnw[d0+5] + lnb[d0+5];
        sn[r*256 + d0 + 6] = (v1.z - mean) * rs * lnw[d0+6] + lnb[d0+6];
        sn[r*256 + d0 + 7] = (v1.w - mean) * rs * lnw[d0+7] + lnb[d0+7];
    }
    __syncthreads();

    {   // MLP1 slice m
        int o = m * 256 + tid;
        float a[8] = {0,0,0,0,0,0,0,0};
        const float4* wr = (const float4*)(w1 + o * 256);
        const float4* sn4 = (const float4*)sn;
        for (int d4 = 0; d4 < 64; d4++) {
            float4 wv = wr[d4];
#pragma unroll
            for (int r = 0; r < 8; r++) {
                float4 s = sn4[r * 64 + d4];
                a[r] += wv.x*s.x + wv.y*s.y + wv.z*s.z + wv.w*s.w;
            }
        }
        float bb = b1[o];
#pragma unroll
        for (int r = 0; r < 8; r++)
            g_h1[(b * 8 + r) * 512 + o] = fmaxf(a[r] + bb, 0.0f);
    }
}

// =================================================================================
// K6dq: MLP2 + residual -> new slots, then (unless last) LN(slots)+q+q~ fused.
// grid 64, 256 threads.
// =================================================================================
__global__ void __launch_bounds__(256) k6dq(
    const float* __restrict__ w2, const float* __restrict__ b2,
    const float* __restrict__ Wq, const float* __restrict__ Wk,
    const float* __restrict__ lnsw, const float* __restrict__ lnsb,
    int last, float* out2)
{
    __shared__ float h1[4096];
    __shared__ float vs[2048];     // new slots
    __shared__ float snq[2048];    // LN(new slots)
    __shared__ float qsm[2048];    // q
    int tid = threadIdx.x, b = blockIdx.x;

    for (int i = tid * 4; i < 4096; i += 1024)
        *(float4*)(h1 + i) = *(const float4*)(g_h1 + b * 4096 + i);
    __syncthreads();

    {   // MLP2 + residual
        int o = tid;
        float a[8] = {0,0,0,0,0,0,0,0};
        const float4* wr = (const float4*)(w2 + o * 512);
        const float4* h14 = (const float4*)h1;
        for (int d4 = 0; d4 < 128; d4++) {
            float4 wv = wr[d4];
#pragma unroll
            for (int r = 0; r < 8; r++) {
                float4 h = h14[r * 128 + d4];
                a[r] += wv.x*h.x + wv.y*h.y + wv.z*h.z + wv.w*h.w;
            }
        }
        float bb = b2[o];
#pragma unroll
        for (int r = 0; r < 8; r++) {
            float vout = g_ns[(b * 8 + r) * 256 + o] + a[r] + bb;
            vs[r * 256 + o] = vout;
            g_slots[(b * 8 + r) * 256 + o] = vout;
            if (last) out2[(b * 8 + r) * 256 + o] = vout;
        }
    }
    if (last) return;
    __syncthreads();

    {   // LN(new slots) -> snq  (ln_slots)
        int r = tid >> 5, l = tid & 31;
        const float4* sr = (const float4*)(vs + r * 256);
        float4 v0 = sr[l * 2], v1 = sr[l * 2 + 1];
        float s1 = v0.x + v0.y + v0.z + v0.w + v1.x + v1.y + v1.z + v1.w;
        float s2 = v0.x*v0.x + v0.y*v0.y + v0.z*v0.z + v0.w*v0.w
                 + v1.x*v1.x + v1.y*v1.y + v1.z*v1.z + v1.w*v1.w;
#pragma unroll
        for (int off = 16; off >= 1; off >>= 1) {
            s1 += __shfl_xor_sync(0xffffffffu, s1, off);
            s2 += __shfl_xor_sync(0xffffffffu, s2, off);
        }
        float mean = s1 * (1.0f / 256.0f);
        float var  = s2 * (1.0f / 256.0f) - mean * mean;
        float rs   = rsqrtf(var + 1e-5f);
        int d0 = l * 8;
        snq[r*256 + d0 + 0] = (v0.x - mean) * rs * lnsw[d0+0] + lnsb[d0+0];
        snq[r*256 + d0 + 1] = (v0.y - mean) * rs * lnsw[d0+1] + lnsb[d0+1];
        snq[r*256 + d0 + 2] = (v0.z - mean) * rs * lnsw[d0+2] + lnsb[d0+2];
        snq[r*256 + d0 + 3] = (v0.w - mean) * rs * lnsw[d0+3] + lnsb[d0+3];
        snq[r*256 + d0 + 4] = (v1.x - mean) * rs * lnsw[d0+4] + lnsb[d0+4];
        snq[r*256 + d0 + 5] = (v1.y - mean) * rs * lnsw[d0+5] + lnsb[d0+5];
        snq[r*256 + d0 + 6] = (v1.z - mean) * rs * lnsw[d0+6] + lnsb[d0+6];
        snq[r*256 + d0 + 7] = (v1.w - mean) * rs * lnsw[d0+7] + lnsb[d0+7];
    }
    __syncthreads();

    {   // q = LN(slots) @ Wq^T * scale
        float acc[8] = {0,0,0,0,0,0,0,0};
        const float4* wr  = (const float4*)(Wq + tid * 256);
        const float4* sn4 = (const float4*)snq;
        for (int d4 = 0; d4 < 64; d4++) {
            float4 w = wr[d4];
#pragma unroll
            for (int rr = 0; rr < 8; rr++) {
                float4 s = sn4[rr * 64 + d4];
                acc[rr] += w.x*s.x + w.y*s.y + w.z*s.z + w.w*s.w;
            }
        }
        const float scale = 0.0625f;
#pragma unroll
        for (int rr = 0; rr < 8; rr++) qsm[rr * 256 + tid] = acc[rr] * scale;
    }
    __syncthreads();

    {   // q~ = q @ Wk -> g_qt
        float a2[8] = {0,0,0,0,0,0,0,0};
#pragma unroll 4
        for (int d = 0; d < 256; d++) {
            float w = __ldg(Wk + d * 256 + tid);
#pragma unroll
            for (int s = 0; s < 8; s++) a2[s] += qsm[s * 256 + d] * w;
        }
#pragma unroll
        for (int s = 0; s < 8; s++)
            g_qt[(b * 8 + s) * 256 + tid] = a2[s];
    }
}

// =================================================================================
extern "C" void kernel_launch(void* const* d_in, const int* in_sizes, int n_in,
                              void* d_out, int out_size) {
    const float* inputs  = (const float*)d_in[0];
    const float* noise   = (const float*)d_in[1];
    const float* ln_in_w = (const float*)d_in[2];
    const float* ln_in_b = (const float*)d_in[3];
    const float* ln_sl_w = (const float*)d_in[4];
    const float* ln_sl_b = (const float*)d_in[5];
    const float* ln_ml_w = (const float*)d_in[6];
    const float* ln_ml_b = (const float*)d_in[7];
    const float* mu      = (const float*)d_in[8];
    const float* ls      = (const float*)d_in[9];
    const float* Wq      = (const float*)d_in[10];
    const float* Wk      = (const float*)d_in[11];
    const float* Wv      = (const float*)d_in[12];
    const float* w_ih    = (const float*)d_in[13];
    const float* w_hh    = (const float*)d_in[14];
    const float* b_ih    = (const float*)d_in[15];
    const float* b_hh    = (const float*)d_in[16];
    const float* w1      = (const float*)d_in[17];
    const float* b1      = (const float*)d_in[18];
    const float* w2      = (const float*)d_in[19];
    const float* b2      = (const float*)d_in[20];
    float* out = (float*)d_out;

    k0_init<<<512, 256>>>(noise, mu, ls);
    k1_ln<<<2048, 256>>>(inputs, ln_in_w, ln_in_b);
    k3_q<<<64, 256>>>(Wq, Wk, ln_sl_w, ln_sl_b);
    for (int it = 0; it < 3; it++) {
        k4_attn<<<dim3(CH_, 64), 256>>>();
        k5_fold<<<64, 256>>>(Wv);
        k6a_gru_gemm<<<dim3(64, 3), 256>>>(w_ih, w_hh, b_ih, b_hh);
        k6bc_gate_ln_mlp1<<<dim3(64, 2), 256>>>(ln_ml_w, ln_ml_b, w1, b1);
        k6dq<<<64, 256>>>(w2, b2, Wq, Wk, ln_sl_w, ln_sl_b,
                          (it == 2) ? 1 : 0, out);
    }
}

// round 17
// speedup vs baseline: 1.5033x; 1.5033x over previous
#include <cuda_runtime.h>

#define B_ 64
#define N_ 4096
#define D_ 256
#define S_ 8
#define H_ 512
#define CH_ 32

// ---------------- scratch (device globals; no allocation allowed) ----------------
__device__ float g_xn[B_*N_*D_];        // LN(inputs)
__device__ float g_slots[B_*S_*D_];
__device__ float g_qt[B_*S_*D_];        // q~ = (q @ Wk)
__device__ float g_upd[B_*S_*D_];       // updates = u @ Wv^T
__device__ float g_updp[B_*CH_*S_*D_];  // partials of u = attn^T @ xn
__device__ float g_colp[B_*CH_*S_];
__device__ float g_gi[B_*S_*768];
__device__ float g_gh[B_*S_*768];
__device__ float g_ns[B_*S_*D_];
__device__ float g_h1[B_*S_*H_];

// ---------------- helpers --------------------------------------------------------
__device__ __forceinline__ void mma_tf32(float& c0, float& c1, float& c2, float& c3,
                                         unsigned a0, unsigned a1, unsigned a2, unsigned a3,
                                         unsigned b0, unsigned b1) {
    asm volatile(
        "mma.sync.aligned.m16n8k8.row.col.f32.tf32.tf32.f32 "
        "{%0,%1,%2,%3}, {%4,%5,%6,%7}, {%8,%9}, {%0,%1,%2,%3};"
        : "+f"(c0), "+f"(c1), "+f"(c2), "+f"(c3)
        : "r"(a0), "r"(a1), "r"(a2), "r"(a3), "r"(b0), "r"(b1));
}

// =================================================================================
// K0: slots = mu + exp(log_sigma) * noise
// =================================================================================
__global__ void k0_init(const float* __restrict__ noise,
                        const float* __restrict__ mu,
                        const float* __restrict__ ls) {
    int i = blockIdx.x * 256 + threadIdx.x;
    int d = i & 255;
    g_slots[i] = mu[d] + expf(ls[d]) * noise[i];
}

// =================================================================================
// K1: xn = LayerNorm(inputs).  grid 2048, 256 threads (2/token).
// =================================================================================
__global__ void __launch_bounds__(256) k1_ln(
    const float* __restrict__ inp, const float* __restrict__ lnw,
    const float* __restrict__ lnb)
{
    int tid = threadIdx.x;
    long tok0 = (long)blockIdx.x * 128;
    int tok = tid >> 1, half = tid & 1;
    const float4* xr = (const float4*)(inp + (tok0 + tok) * 256 + half * 128);
    float4 t[32];
    float s1 = 0.f, s2 = 0.f;
#pragma unroll
    for (int j = 0; j < 32; j++) {
        t[j] = xr[j];
        s1 += t[j].x + t[j].y + t[j].z + t[j].w;
        s2 += t[j].x*t[j].x + t[j].y*t[j].y + t[j].z*t[j].z + t[j].w*t[j].w;
    }
    s1 += __shfl_xor_sync(0xffffffffu, s1, 1);
    s2 += __shfl_xor_sync(0xffffffffu, s2, 1);
    float mean = s1 * (1.0f / 256.0f);
    float var  = s2 * (1.0f / 256.0f) - mean * mean;
    float rs   = rsqrtf(var + 1e-5f);
    const float4* lw4 = (const float4*)(lnw + half * 128);
    const float4* lb4 = (const float4*)(lnb + half * 128);
    float4* xw = (float4*)(g_xn + (tok0 + tok) * 256 + half * 128);
#pragma unroll
    for (int j = 0; j < 32; j++) {
        float4 w4 = __ldg(lw4 + j);
        float4 b4 = __ldg(lb4 + j);
        float4 o;
        o.x = (t[j].x - mean) * rs * w4.x + b4.x;
        o.y = (t[j].y - mean) * rs * w4.y + b4.y;
        o.z = (t[j].z - mean) * rs * w4.z + b4.z;
        o.w = (t[j].w - mean) * rs * w4.w + b4.w;
        xw[j] = o;
    }
}

// =================================================================================
// K3: q = LN(slots) @ Wq^T * scale, then q~ = q @ Wk.  grid 64, 256 threads.
// =================================================================================
__global__ void __launch_bounds__(256) k3_q(
    const float* __restrict__ Wq, const float* __restrict__ Wk,
    const float* __restrict__ lnw, const float* __restrict__ lnb)
{
    __shared__ float sn[8 * 256];
    __shared__ float qsm[8 * 256];
    int tid = threadIdx.x, b = blockIdx.x;
    int r = tid >> 5, l = tid & 31;

    const float4* sr = (const float4*)(g_slots + (b * 8 + r) * 256);
    float4 v0 = sr[l * 2], v1 = sr[l * 2 + 1];
    float s1 = v0.x + v0.y + v0.z + v0.w + v1.x + v1.y + v1.z + v1.w;
    float s2 = v0.x*v0.x + v0.y*v0.y + v0.z*v0.z + v0.w*v0.w
             + v1.x*v1.x + v1.y*v1.y + v1.z*v1.z + v1.w*v1.w;
#pragma unroll
    for (int off = 16; off >= 1; off >>= 1) {
        s1 += __shfl_xor_sync(0xffffffffu, s1, off);
        s2 += __shfl_xor_sync(0xffffffffu, s2, off);
    }
    float mean = s1 * (1.0f / 256.0f);
    float var  = s2 * (1.0f / 256.0f) - mean * mean;
    float rs   = rsqrtf(var + 1e-5f);
    int d0 = l * 8;
    sn[r*256 + d0 + 0] = (v0.x - mean) * rs * lnw[d0+0] + lnb[d0+0];
    sn[r*256 + d0 + 1] = (v0.y - mean) * rs * lnw[d0+1] + lnb[d0+1];
    sn[r*256 + d0 + 2] = (v0.z - mean) * rs * lnw[d0+2] + lnb[d0+2];
    sn[r*256 + d0 + 3] = (v0.w - mean) * rs * lnw[d0+3] + lnb[d0+3];
    sn[r*256 + d0 + 4] = (v1.x - mean) * rs * lnw[d0+4] + lnb[d0+4];
    sn[r*256 + d0 + 5] = (v1.y - mean) * rs * lnw[d0+5] + lnb[d0+5];
    sn[r*256 + d0 + 6] = (v1.z - mean) * rs * lnw[d0+6] + lnb[d0+6];
    sn[r*256 + d0 + 7] = (v1.w - mean) * rs * lnw[d0+7] + lnb[d0+7];
    __syncthreads();

    {
        float acc[8] = {0,0,0,0,0,0,0,0};
        const float4* wr  = (const float4*)(Wq + tid * 256);
        const float4* sn4 = (const float4*)sn;
        for (int d4 = 0; d4 < 64; d4++) {
            float4 w = wr[d4];
#pragma unroll
            for (int rr = 0; rr < 8; rr++) {
                float4 s = sn4[rr * 64 + d4];
                acc[rr] += w.x*s.x + w.y*s.y + w.z*s.z + w.w*s.w;
            }
        }
        const float scale = 0.0625f;
#pragma unroll
        for (int rr = 0; rr < 8; rr++) qsm[rr * 256 + tid] = acc[rr] * scale;
    }
    __syncthreads();

    {
        float a2[8] = {0,0,0,0,0,0,0,0};
#pragma unroll 4
        for (int d = 0; d < 256; d++) {
            float w = __ldg(Wk + d * 256 + tid);
#pragma unroll
            for (int s = 0; s < 8; s++) a2[s] += qsm[s * 256 + d] * w;
        }
#pragma unroll
        for (int s = 0; s < 8; s++)
            g_qt[(b * 8 + s) * 256 + tid] = a2[s];
    }
}

// =================================================================================
// K4: smem-free tf32 streaming attention on xn (R12 verbatim, occ 3).  grid (32,64).
// =================================================================================
__global__ void __launch_bounds__(256, 3) k4_attn()
{
    __shared__ float at[16 * 132];
    __shared__ unsigned qt[256 * 8];
    __shared__ float wcs[8][8];
    unsigned* atu = (unsigned*)at;

    int tid = threadIdx.x;
    int w = tid >> 5, lane = tid & 31;
    int g = lane >> 2, c = lane & 3;
    int b = blockIdx.y, chunk = blockIdx.x;
    long tok0 = (long)b * 4096 + (long)chunk * 128;

    for (int i = tid; i < 2048; i += 256) {
        int s = i >> 8, d = i & 255;
        qt[d * 8 + s] = __float_as_uint(g_qt[b * 2048 + i]);
    }
    for (int i = tid; i < 8 * 132; i += 256) at[8 * 132 + i] = 0.f;
    __syncthreads();

    {   // phase 1: warp w -> tokens [w*16, w*16+16)
        int m0 = w * 16;
        const unsigned* kb = (const unsigned*)(g_xn + tok0 * 256);
        int rA = (m0 + g) * 256, rB = (m0 + g + 8) * 256;
        float c0 = 0.f, c1 = 0.f, c2 = 0.f, c3 = 0.f;
#pragma unroll 8
        for (int ks = 0; ks < 32; ks++) {
            int k0 = ks * 8;
            unsigned a0 = kb[rA + k0 + c];
            unsigned a1 = kb[rB + k0 + c];
            unsigned a2 = kb[rA + k0 + c + 4];
            unsigned a3 = kb[rB + k0 + c + 4];
            unsigned b0 = qt[(k0 + c) * 8 + g];
            unsigned b1 = qt[(k0 + c + 4) * 8 + g];
            mma_tf32(c0, c1, c2, c3, a0, a1, a2, a3, b0, b1);
        }
        float cs0 = 0.f, cs1 = 0.f;
        {
            float m1 = fmaxf(c0, c1);
            m1 = fmaxf(m1, __shfl_xor_sync(0xffffffffu, m1, 1));
            m1 = fmaxf(m1, __shfl_xor_sync(0xffffffffu, m1, 2));
            float e0 = expf(c0 - m1), e1 = expf(c1 - m1);
            float sv = e0 + e1;
            sv += __shfl_xor_sync(0xffffffffu, sv, 1);
            sv += __shfl_xor_sync(0xffffffffu, sv, 2);
            float inv = 1.0f / sv;
            float w0 = e0 * inv + 1e-8f, w1v = e1 * inv + 1e-8f;
            at[(2*c)   * 132 + m0 + g] = w0;
            at[(2*c+1) * 132 + m0 + g] = w1v;
            cs0 += w0; cs1 += w1v;
        }
        {
            float m1 = fmaxf(c2, c3);
            m1 = fmaxf(m1, __shfl_xor_sync(0xffffffffu, m1, 1));
            m1 = fmaxf(m1, __shfl_xor_sync(0xffffffffu, m1, 2));
            float e0 = expf(c2 - m1), e1 = expf(c3 - m1);
            float sv = e0 + e1;
            sv += __shfl_xor_sync(0xffffffffu, sv, 1);
            sv += __shfl_xor_sync(0xffffffffu, sv, 2);
            float inv = 1.0f / sv;
            float w0 = e0 * inv + 1e-8f, w1v = e1 * inv + 1e-8f;
            at[(2*c)   * 132 + m0 + g + 8] = w0;
            at[(2*c+1) * 132 + m0 + g + 8] = w1v;
            cs0 += w0; cs1 += w1v;
        }
        cs0 += __shfl_xor_sync(0xffffffffu, cs0, 4);
        cs1 += __shfl_xor_sync(0xffffffffu, cs1, 4);
        cs0 += __shfl_xor_sync(0xffffffffu, cs0, 8);
        cs1 += __shfl_xor_sync(0xffffffffu, cs1, 8);
        cs0 += __shfl_xor_sync(0xffffffffu, cs0, 16);
        cs1 += __shfl_xor_sync(0xffffffffu, cs1, 16);
        if (g == 0) { wcs[w][2*c] = cs0; wcs[w][2*c + 1] = cs1; }
    }
    __syncthreads();
    if (tid < 8) {
        float s = 0.f;
#pragma unroll
        for (int wi = 0; wi < 8; wi++) s += wcs[wi][tid];
        g_colp[(b * CH_ + chunk) * 8 + tid] = s;
    }

    {   // phase 2: warp w -> dims [w*32, w*32+32) (same xn tile, L2-hot)
        const unsigned* vb = (const unsigned*)(g_xn + tok0 * 256);
        float acc[4][4];
#pragma unroll
        for (int nt = 0; nt < 4; nt++)
#pragma unroll
            for (int e = 0; e < 4; e++) acc[nt][e] = 0.f;
#pragma unroll 2
        for (int ks = 0; ks < 16; ks++) {
            int k0 = ks * 8;
            unsigned a0 = atu[g * 132 + k0 + c];
            unsigned a1 = atu[(g + 8) * 132 + k0 + c];
            unsigned a2 = atu[g * 132 + k0 + c + 4];
            unsigned a3 = atu[(g + 8) * 132 + k0 + c + 4];
            int rc = (k0 + c) * 256, rc4 = (k0 + c + 4) * 256;
#pragma unroll
            for (int nt = 0; nt < 4; nt++) {
                int n0 = w * 32 + nt * 8 + g;
                unsigned b0 = vb[rc + n0];
                unsigned b1 = vb[rc4 + n0];
                mma_tf32(acc[nt][0], acc[nt][1], acc[nt][2], acc[nt][3],
                         a0, a1, a2, a3, b0, b1);
            }
        }
        float* op = g_updp + ((long)(b * CH_ + chunk) * 8 + g) * 256;
#pragma unroll
        for (int nt = 0; nt < 4; nt++) {
            int n0 = w * 32 + nt * 8;
            *(float2*)(op + n0 + 2 * c) = make_float2(acc[nt][0], acc[nt][1]);
        }
    }
}

// =================================================================================
// K5: chunk-reduce (float4) + colsum-normalize + updates = u @ Wv^T.  grid 64.
// =================================================================================
__global__ void __launch_bounds__(256) k5_fold(const float* __restrict__ Wv)
{
    __shared__ float up[2048], cs[8];
    int tid = threadIdx.x, b = blockIdx.x;

    {
        int s = tid >> 5, l = tid & 31;
        float c = g_colp[(b * CH_ + l) * 8 + s];
#pragma unroll
        for (int off = 16; off >= 1; off >>= 1)
            c += __shfl_xor_sync(0xffffffffu, c, off);
        if (l == 0) cs[s] = c;
    }
    __syncthreads();

    for (int i = tid * 4; i < 2048; i += 1024) {
        const float4* p = (const float4*)(g_updp + (long)b * CH_ * 2048 + i);
        float4 a = make_float4(0.f, 0.f, 0.f, 0.f);
#pragma unroll 8
        for (int ch = 0; ch < CH_; ch++) {
            float4 t = p[ch * 512];
            a.x += t.x; a.y += t.y; a.z += t.z; a.w += t.w;
        }
        float inv = 1.0f / cs[i >> 8];
        a.x *= inv; a.y *= inv; a.z *= inv; a.w *= inv;
        *(float4*)(up + i) = a;
    }
    __syncthreads();

    {   // updates = u @ Wv^T
        float au[8] = {0,0,0,0,0,0,0,0};
        const float4* wv4 = (const float4*)(Wv + tid * 256);
        const float4* up4 = (const float4*)up;
        for (int d4 = 0; d4 < 64; d4++) {
            float4 wv = wv4[d4];
#pragma unroll
            for (int r = 0; r < 8; r++) {
                float4 u = up4[r * 64 + d4];
                au[r] += wv.x*u.x + wv.y*u.y + wv.z*u.z + wv.w*u.w;
            }
        }
#pragma unroll
        for (int r = 0; r < 8; r++)
            g_upd[(b * 8 + r) * 256 + tid] = au[r];
    }
}

// =================================================================================
// K6a: GRU gemms only.  grid (64, 3), 256 threads.
// =================================================================================
__global__ void __launch_bounds__(256) k6a_gru_gemm(
    const float* __restrict__ w_ih, const float* __restrict__ w_hh,
    const float* __restrict__ b_ih, const float* __restrict__ b_hh)
{
    __shared__ float updm[2048], hp[2048];
    int tid = threadIdx.x, b = blockIdx.x, m = blockIdx.y;

    for (int i = tid; i < 2048; i += 256) {
        updm[i] = g_upd[b * 2048 + i];
        hp[i]   = g_slots[b * 2048 + i];
    }
    __syncthreads();

    int o = m * 256 + tid;
    float ai[8] = {0,0,0,0,0,0,0,0};
    float ah[8] = {0,0,0,0,0,0,0,0};
    const float4* wi = (const float4*)(w_ih + o * 256);
    const float4* wh = (const float4*)(w_hh + o * 256);
    const float4* ud4 = (const float4*)updm;
    const float4* hp4 = (const float4*)hp;
    for (int d4 = 0; d4 < 64; d4++) {
        float4 a = wi[d4];
        float4 cH = wh[d4];
#pragma unroll
        for (int r = 0; r < 8; r++) {
            float4 u = ud4[r * 64 + d4];
            float4 h = hp4[r * 64 + d4];
            ai[r] += a.x*u.x + a.y*u.y + a.z*u.z + a.w*u.w;
            ah[r] += cH.x*h.x + cH.y*h.y + cH.z*h.z + cH.w*h.w;
        }
    }
    float bi = b_ih[o], bh = b_hh[o];
#pragma unroll
    for (int r = 0; r < 8; r++) {
        g_gi[(b * 8 + r) * 768 + o] = ai[r] + bi;
        g_gh[(b * 8 + r) * 768 + o] = ah[r] + bh;
    }
}

// =================================================================================
// K6bc: gates + LN (recomputed per y-block) + MLP1 slice.  grid (64, 2), 256 thr.
// =================================================================================
__global__ void __launch_bounds__(256) k6bc_gate_ln_mlp1(
    const float* __restrict__ lnw, const float* __restrict__ lnb,
    const float* __restrict__ w1,  const float* __restrict__ b1)
{
    __shared__ float ns[2048];
    __shared__ float sn[2048];
    int tid = threadIdx.x, b = blockIdx.x, m = blockIdx.y;
    int d = tid;
#pragma unroll
    for (int r = 0; r < 8; r++) {
        long base = (long)(b * 8 + r) * 768;
        float ir = g_gi[base + d],       hr = g_gh[base + d];
        float iz = g_gi[base + 256 + d], hz = g_gh[base + 256 + d];
        float in_ = g_gi[base + 512 + d], hn = g_gh[base + 512 + d];
        float rg = 1.0f / (1.0f + expf(-(ir + hr)));
        float zg = 1.0f / (1.0f + expf(-(iz + hz)));
        float ng = tanhf(in_ + rg * hn);
        float h = g_slots[(b * 8 + r) * 256 + d];
        float nsv = (1.0f - zg) * ng + zg * h;
        ns[r * 256 + d] = nsv;
        if (m == 0) g_ns[(b * 8 + r) * 256 + d] = nsv;
    }
    __syncthreads();

    {   // LN(ns) -> sn (smem only)
        int r = tid >> 5, l = tid & 31;
        const float4* nr = (const float4*)(ns + r * 256);
        float4 v0 = nr[l * 2], v1 = nr[l * 2 + 1];
        float s1 = v0.x + v0.y + v0.z + v0.w + v1.x + v1.y + v1.z + v1.w;
        float s2 = v0.x*v0.x + v0.y*v0.y + v0.z*v0.z + v0.w*v0.w
                 + v1.x*v1.x + v1.y*v1.y + v1.z*v1.z + v1.w*v1.w;
#pragma unroll
        for (int off = 16; off >= 1; off >>= 1) {
            s1 += __shfl_xor_sync(0xffffffffu, s1, off);
            s2 += __shfl_xor_sync(0xffffffffu, s2, off);
        }
        float mean = s1 * (1.0f / 256.0f);
        float var  = s2 * (1.0f / 256.0f) - mean * mean;
        float rs   = rsqrtf(var + 1e-5f);
        int d0 = l * 8;
        sn[r*256 + d0 + 0] = (v0.x - mean) * rs * lnw[d0+0] + lnb[d0+0];
        sn[r*256 + d0 + 1] = (v0.y - mean) * rs * lnw[d0+1] + lnb[d0+1];
        sn[r*256 + d0 + 2] = (v0.z - mean) * rs * lnw[d0+2] + lnb[d0+2];
        sn[r*256 + d0 + 3] = (v0.w - mean) * rs * lnw[d0+3] + lnb[d0+3];
        sn[r*256 + d0 + 4] = (v1.x - mean) * rs * lnw[d0+4] + lnb[d0+4];
        sn[r*256 + d0 + 5] = (v1.y - mean) * rs * lnw[d0+5] + lnb[d0+5];
        sn[r*256 + d0 + 6] = (v1.z - mean) * rs * lnw[d0+6] + lnb[d0+6];
        sn[r*256 + d0 + 7] = (v1.w - mean) * rs * lnw[d0+7] + lnb[d0+7];
    }
    __syncthreads();

    {   // MLP1 slice m
        int o = m * 256 + tid;
        float a[8] = {0,0,0,0,0,0,0,0};
        const float4* wr = (const float4*)(w1 + o * 256);
        const float4* sn4 = (const float4*)sn;
        for (int d4 = 0; d4 < 64; d4++) {
            float4 wv = wr[d4];
#pragma unroll
            for (int r = 0; r < 8; r++) {
                float4 s = sn4[r * 64 + d4];
                a[r] += wv.x*s.x + wv.y*s.y + wv.z*s.z + wv.w*s.w;
            }
        }
        float bb = b1[o];
#pragma unroll
        for (int r = 0; r < 8; r++)
            g_h1[(b * 8 + r) * 512 + o] = fmaxf(a[r] + bb, 0.0f);
    }
}

// =================================================================================
// K6d: out = ns + h1 @ w2^T + b2.  grid (64, 2), 128 threads.
// =================================================================================
__global__ void __launch_bounds__(128) k6d_mlp2(
    const float* __restrict__ w2, const float* __restrict__ b2, float* out2)
{
    __shared__ float h1[4096];
    int tid = threadIdx.x, b = blockIdx.x, half = blockIdx.y;
    for (int i = tid * 4; i < 4096; i += 512)
        *(float4*)(h1 + i) = *(const float4*)(g_h1 + b * 4096 + i);
    __syncthreads();

    int o = half * 128 + tid;
    float a[8] = {0,0,0,0,0,0,0,0};
    const float4* wr = (const float4*)(w2 + o * 512);
    const float4* h14 = (const float4*)h1;
    for (int d4 = 0; d4 < 128; d4++) {
        float4 wv = wr[d4];
#pragma unroll
        for (int r = 0; r < 8; r++) {
            float4 h = h14[r * 128 + d4];
            a[r] += wv.x*h.x + wv.y*h.y + wv.z*h.z + wv.w*h.w;
        }
    }
    float bb = b2[o];
#pragma unroll
    for (int r = 0; r < 8; r++) {
        float vout = g_ns[(b * 8 + r) * 256 + o] + a[r] + bb;
        g_slots[(b * 8 + r) * 256 + o] = vout;
        if (out2) out2[(b * 8 + r) * 256 + o] = vout;
    }
}

// =================================================================================
extern "C" void kernel_launch(void* const* d_in, const int* in_sizes, int n_in,
                              void* d_out, int out_size) {
    const float* inputs  = (const float*)d_in[0];
    const float* noise   = (const float*)d_in[1];
    const float* ln_in_w = (const float*)d_in[2];
    const float* ln_in_b = (const float*)d_in[3];
    const float* ln_sl_w = (const float*)d_in[4];
    const float* ln_sl_b = (const float*)d_in[5];
    const float* ln_ml_w = (const float*)d_in[6];
    const float* ln_ml_b = (const float*)d_in[7];
    const float* mu      = (const float*)d_in[8];
    const float* ls      = (const float*)d_in[9];
    const float* Wq      = (const float*)d_in[10];
    const float* Wk      = (const float*)d_in[11];
    const float* Wv      = (const float*)d_in[12];
    const float* w_ih    = (const float*)d_in[13];
    const float* w_hh    = (const float*)d_in[14];
    const float* b_ih    = (const float*)d_in[15];
    const float* b_hh    = (const float*)d_in[16];
    const float* w1      = (const float*)d_in[17];
    const float* b1      = (const float*)d_in[18];
    const float* w2      = (const float*)d_in[19];
    const float* b2      = (const float*)d_in[20];
    float* out = (float*)d_out;

    k0_init<<<512, 256>>>(noise, mu, ls);
    k1_ln<<<2048, 256>>>(inputs, ln_in_w, ln_in_b);
    for (int it = 0; it < 3; it++) {
        k3_q<<<64, 256>>>(Wq, Wk, ln_sl_w, ln_sl_b);
        k4_attn<<<dim3(CH_, 64), 256>>>();
        k5_fold<<<64, 256>>>(Wv);
        k6a_gru_gemm<<<dim3(64, 3), 256>>>(w_ih, w_hh, b_ih, b_hh);
        k6bc_gate_ln_mlp1<<<dim3(64, 2), 256>>>(ln_ml_w, ln_ml_b, w1, b1);
        k6d_mlp2<<<dim3(64, 2), 128>>>(w2, b2, (it == 2) ? out : nullptr);
    }
}